// round 12
// baseline (speedup 1.0000x reference)
#include <cuda_runtime.h>
#include <cuda_fp16.h>
#include <cstdint>

// ---------------------------------------------------------------------------
// Problem constants
// ---------------------------------------------------------------------------
#define BS      2
#define SEQ     4096
#define DMODEL  768
#define HEADS   12
#define DK      64
#define MROWS   (BS * SEQ)          // 8192

// ---------------------------------------------------------------------------
// Scratch (device globals; no cudaMalloc allowed)
// ---------------------------------------------------------------------------
__device__ __half g_Qp[MROWS * DMODEL];              // prescaled by log2e/8
__device__ __half g_Kp[MROWS * DMODEL];
__device__ __half g_Vt[(size_t)BS * DMODEL * SEQ];   // [b][dmodel][seq]
__device__ float  g_Ctx[MROWS * DMODEL];

// ---------------------------------------------------------------------------
// Helpers
// ---------------------------------------------------------------------------
__device__ __forceinline__ void mma16(float* d, const uint32_t* a,
                                      uint32_t b0, uint32_t b1) {
    asm volatile(
        "mma.sync.aligned.m16n8k16.row.col.f32.f16.f16.f32 "
        "{%0,%1,%2,%3}, {%4,%5,%6,%7}, {%8,%9}, {%0,%1,%2,%3};"
        : "+f"(d[0]), "+f"(d[1]), "+f"(d[2]), "+f"(d[3])
        : "r"(a[0]), "r"(a[1]), "r"(a[2]), "r"(a[3]), "r"(b0), "r"(b1));
}

__device__ __forceinline__ uint32_t packh2(float a, float b) {
    __half2 h = __floats2half2_rn(a, b);
    return *(uint32_t*)&h;
}

__device__ __forceinline__ uint32_t ex2h2(uint32_t x) {
    uint32_t r;
    asm("ex2.approx.f16x2 %0, %1;" : "=r"(r) : "r"(x));
    return r;
}

__device__ __forceinline__ void st_h4(__half* p, float4 v) {
    uint2 u;
    u.x = packh2(v.x, v.y);
    u.y = packh2(v.z, v.w);
    *(uint2*)p = u;
}

__device__ __forceinline__ void cpa16r(uint32_t dst, const void* src) {
    asm volatile("cp.async.cg.shared.global [%0], [%1], 16;"
                 :: "r"(dst), "l"(src));
}
#define CPA_COMMIT() asm volatile("cp.async.commit_group;" ::: "memory")
#define CPA_WAIT1()  asm volatile("cp.async.wait_group 1;" ::: "memory")
#define CPA_WAIT0()  asm volatile("cp.async.wait_group 0;" ::: "memory")

// ---------------------------------------------------------------------------
// GEMM body: C[M,N] = (A @ B^T + bias) * scale, M=8192, N=K=768 (all 4 GEMMs).
// 128x128 tile, BK=32, 256 threads = 8 warps (4m x 2n), warp tile 32x64.
// trans!=0: write C transposed per batch (Vt layout).
// ---------------------------------------------------------------------------
#define GBM 128
#define GBN 128
#define GBK 32
#define GLDH 40

template <typename OutT>
__device__ __forceinline__ void gemm_body(
    const float* __restrict__ A, const float* __restrict__ B,
    const float* __restrict__ bias, OutT* __restrict__ C,
    float scale, int trans, __half* As, __half* Bs)
{
    const int N = DMODEL, K = DMODEL;
    const int tid = threadIdx.x;
    const int lane = tid & 31, wid = tid >> 5;
    const int g = lane >> 2, tig = lane & 3;
    const int wm = (wid & 3) * 32, wn = (wid >> 2) * 64;
    const int row0 = blockIdx.y * GBM, col0 = blockIdx.x * GBN;

    const int r = tid >> 3;
    const int c4 = (tid & 7) * 4;
    const float* Aptr = A + (size_t)(row0 + r) * K + c4;
    const float* Bptr = B + (size_t)(col0 + r) * K + c4;

    float4 pa[4], pb[4];
    #pragma unroll
    for (int m = 0; m < 4; m++) {
        pa[m] = *(const float4*)(Aptr + (size_t)(32 * m) * K);
        pb[m] = *(const float4*)(Bptr + (size_t)(32 * m) * K);
    }

    float acc[2][8][4] = {};

    int k0 = 0;
    while (true) {
        __syncthreads();
        #pragma unroll
        for (int m = 0; m < 4; m++) {
            st_h4(As + (r + 32 * m) * GLDH + c4, pa[m]);
            st_h4(Bs + (r + 32 * m) * GLDH + c4, pb[m]);
        }
        __syncthreads();

        k0 += GBK;
        const bool more = (k0 < K);
        if (more) {
            #pragma unroll
            for (int m = 0; m < 4; m++) {
                pa[m] = *(const float4*)(Aptr + (size_t)(32 * m) * K + k0);
                pb[m] = *(const float4*)(Bptr + (size_t)(32 * m) * K + k0);
            }
        }

        #pragma unroll
        for (int c = 0; c < 2; c++) {
            const int kk = 16 * c + 2 * tig;
            uint32_t a[2][4];
            #pragma unroll
            for (int i = 0; i < 2; i++) {
                const int rb = wm + 16 * i;
                a[i][0] = *(const uint32_t*)&As[(rb + g) * GLDH + kk];
                a[i][1] = *(const uint32_t*)&As[(rb + 8 + g) * GLDH + kk];
                a[i][2] = *(const uint32_t*)&As[(rb + g) * GLDH + kk + 8];
                a[i][3] = *(const uint32_t*)&As[(rb + 8 + g) * GLDH + kk + 8];
            }
            #pragma unroll
            for (int j = 0; j < 8; j++) {
                const int cn = wn + j * 8 + g;
                uint32_t b0 = *(const uint32_t*)&Bs[cn * GLDH + kk];
                uint32_t b1 = *(const uint32_t*)&Bs[cn * GLDH + kk + 8];
                mma16(acc[0][j], a[0], b0, b1);
                mma16(acc[1][j], a[1], b0, b1);
            }
        }
        if (!more) break;
    }

    #pragma unroll
    for (int i = 0; i < 2; i++) {
        const int rA = row0 + wm + i * 16 + g;
        const int rB = rA + 8;
        #pragma unroll
        for (int j = 0; j < 8; j++) {
            const int col = col0 + wn + j * 8 + 2 * tig;
            const float bx = __ldg(bias + col), by = __ldg(bias + col + 1);
            const float v0 = (acc[i][j][0] + bx) * scale;
            const float v1 = (acc[i][j][1] + by) * scale;
            const float v2 = (acc[i][j][2] + bx) * scale;
            const float v3 = (acc[i][j][3] + by) * scale;
            if (!trans) {
                if (sizeof(OutT) == 2) {
                    __half2* pA = (__half2*)((__half*)C + (size_t)rA * N + col);
                    __half2* pB = (__half2*)((__half*)C + (size_t)rB * N + col);
                    *pA = __floats2half2_rn(v0, v1);
                    *pB = __floats2half2_rn(v2, v3);
                } else {
                    *(float2*)((float*)C + (size_t)rA * N + col) = make_float2(v0, v1);
                    *(float2*)((float*)C + (size_t)rB * N + col) = make_float2(v2, v3);
                }
            } else {
                const int bA = rA >> 12, sA = rA & (SEQ - 1);
                const int bB = rB >> 12, sB = rB & (SEQ - 1);
                C[((size_t)bA * DMODEL + col)     * SEQ + sA] = (OutT)v0;
                C[((size_t)bA * DMODEL + col + 1) * SEQ + sA] = (OutT)v1;
                C[((size_t)bB * DMODEL + col)     * SEQ + sB] = (OutT)v2;
                C[((size_t)bB * DMODEL + col + 1) * SEQ + sB] = (OutT)v3;
            }
        }
    }
}

// merged Q/K/V projection: blockIdx.z selects which GEMM this CTA computes
__global__ __launch_bounds__(256, 2) void qkv_gemm(
    const float* __restrict__ q, const float* __restrict__ k,
    const float* __restrict__ v,
    const float* __restrict__ Wq, const float* __restrict__ bq,
    const float* __restrict__ Wk, const float* __restrict__ bk,
    const float* __restrict__ Wv, const float* __restrict__ bv,
    __half* __restrict__ Qp, __half* __restrict__ Kp, __half* __restrict__ Vt,
    float qscale)
{
    __shared__ __half As[GBM * GLDH];
    __shared__ __half Bs[GBN * GLDH];
    const int z = blockIdx.z;
    const float* A  = (z == 0) ? q  : (z == 1) ? k  : v;
    const float* W  = (z == 0) ? Wq : (z == 1) ? Wk : Wv;
    const float* bb = (z == 0) ? bq : (z == 1) ? bk : bv;
    __half* C       = (z == 0) ? Qp : (z == 1) ? Kp : Vt;
    const float sc  = (z == 0) ? qscale : 1.0f;
    gemm_body<__half>(A, W, bb, C, sc, z == 2, As, Bs);
}

__global__ __launch_bounds__(256, 2) void o_gemm(
    const float* __restrict__ Ctx, const float* __restrict__ Wo,
    const float* __restrict__ bo, float* __restrict__ out)
{
    __shared__ __half As[GBM * GLDH];
    __shared__ __half Bs[GBN * GLDH];
    gemm_body<float>(Ctx, Wo, bo, out, 1.0f, 0, As, Bs);
}

// ---------------------------------------------------------------------------
// Attention: fp16 mma, 32-q warp tiles, 3-stage cp.async pipeline with ONE
// barrier per tile. Softmax in exp2 domain via ex2.f16x2; row sums via
// ones-MMA. CTA = (b, h, 128-query tile), 128 threads = 4 warps x 32 q-rows.
// Buffer rotation safety: tile kt+2 goes to buffer (kt+2)%3 = (kt-1)%3,
// whose readers (tile kt-1 compute) all passed the tile-kt barrier first.
// ---------------------------------------------------------------------------
#define KLD 72
#define NT  (SEQ / 64)
#define BUFB  (128 * KLD * 2)           // bytes per KV buffer
#define ATT_SMEM (3 * BUFB)             // 55296 bytes (dynamic)

__global__ void __launch_bounds__(128, 3)
attn_tc(const __half* __restrict__ Qp, const __half* __restrict__ Kp,
        const __half* __restrict__ Vt, const int* __restrict__ mask,
        float* __restrict__ Ctx)
{
    extern __shared__ __half KV[];      // [3][128*KLD]

    const int tid = threadIdx.x;
    const int lane = tid & 31, wid = tid >> 5;
    const int g = lane >> 2, tig = lane & 3;
    const int b = blockIdx.y / HEADS, h = blockIdx.y % HEADS;
    const int q0 = blockIdx.x * 128;
    const int qb = wid * 32;

    const __half* kg = Kp + ((size_t)b * SEQ) * DMODEL + h * DK;
    const __half* vg = Vt + ((size_t)(b * DMODEL + h * DK)) * SEQ;
    const int* mg = mask + b * SEQ;

    // ---- stage Q (fp16, pre-scaled) through buffer 0, lift A-frags ----
    {
        const __half* qg = Qp + ((size_t)(b * SEQ + q0)) * DMODEL + h * DK;
        #pragma unroll
        for (int i = 0; i < 8; i++) {
            const int L = tid + i * 128;
            const int r = L >> 3, c8 = (L & 7) * 8;
            *(uint4*)(KV + r * KLD + c8) =
                *(const uint4*)(qg + (size_t)r * DMODEL + c8);
        }
    }
    __syncthreads();

    uint32_t qf[4][2][4];
    #pragma unroll
    for (int c = 0; c < 4; c++) {
        const int kk = 16 * c + 2 * tig;
        #pragma unroll
        for (int i = 0; i < 2; i++) {
            const int rb = qb + 16 * i;
            qf[c][i][0] = *(const uint32_t*)&KV[(rb + g) * KLD + kk];
            qf[c][i][1] = *(const uint32_t*)&KV[(rb + 8 + g) * KLD + kk];
            qf[c][i][2] = *(const uint32_t*)&KV[(rb + g) * KLD + kk + 8];
            qf[c][i][3] = *(const uint32_t*)&KV[(rb + 8 + g) * KLD + kk + 8];
        }
    }
    __syncthreads();

    // ---- hoisted prefetch addressing ----
    const int pr = tid >> 3;              // 0..15
    const int pc = (tid & 7) * 8;         // 0..56
    const __half* ksrc = kg + (size_t)pr * DMODEL + pc;
    const __half* vsrc = vg + (size_t)pr * SEQ + pc;
    const uint32_t dk0 =
        (uint32_t)__cvta_generic_to_shared(&KV[pr * KLD + pc]);

    float o[2][8][4] = {};
    float lacc[2][4] = {};               // ones-MMA row-sum accumulators
    const uint32_t ONE2 = 0x3C003C00u;   // half2(1.0, 1.0)
    const float NEGINF = __int_as_float(0xff800000);

    // prologue: prefetch tiles 0 and 1 into buffers 0 and 1
    #pragma unroll
    for (int t = 0; t < 2; t++) {
        const uint32_t dK = dk0 + t * BUFB;
        const uint32_t dV = dK + 64 * KLD * 2;
        #pragma unroll
        for (int i = 0; i < 4; i++) {
            cpa16r(dK + i * (16 * KLD * 2), ksrc + (size_t)i * 16 * DMODEL);
            cpa16r(dV + i * (16 * KLD * 2), vsrc + (size_t)i * 16 * SEQ);
        }
        CPA_COMMIT();
        ksrc += (size_t)64 * DMODEL;
        vsrc += 64;
    }

    int cur = 0, nxt = 2;                 // buffer indices (mod 3)
    for (int kt = 0; kt < NT; kt++) {
        const __half* Ks = KV + cur * (128 * KLD);
        const __half* Vs = Ks + 64 * KLD;

        const int mv = __ldg(mg + kt * 64 + (tid & 63));

        if (kt + 1 < NT) { CPA_WAIT1(); } else { CPA_WAIT0(); }
        const int allone = __syncthreads_and(mv != 0);

        if (kt + 2 < NT) {
            const uint32_t dK = dk0 + nxt * BUFB;
            const uint32_t dV = dK + 64 * KLD * 2;
            #pragma unroll
            for (int i = 0; i < 4; i++) {
                cpa16r(dK + i * (16 * KLD * 2), ksrc + (size_t)i * 16 * DMODEL);
                cpa16r(dV + i * (16 * KLD * 2), vsrc + (size_t)i * 16 * SEQ);
            }
            CPA_COMMIT();
            ksrc += (size_t)64 * DMODEL;
            vsrc += 64;
        }
        cur = (cur == 2) ? 0 : cur + 1;
        nxt = (nxt == 2) ? 0 : nxt + 1;

        // ---- S = Q K^T (exp2-domain scores) ----
        float s[2][8][4] = {};
        #pragma unroll
        for (int c = 0; c < 4; c++) {
            const int kk = 16 * c + 2 * tig;
            #pragma unroll
            for (int j = 0; j < 8; j++) {
                const int rn = (j * 8 + g) * KLD + kk;
                uint32_t b0 = *(const uint32_t*)&Ks[rn];
                uint32_t b1 = *(const uint32_t*)&Ks[rn + 8];
                mma16(s[0][j], qf[c][0], b0, b1);
                mma16(s[1][j], qf[c][1], b0, b1);
            }
        }

        // ---- mask (rare path): poison scores with -inf ----
        if (!allone) {
            #pragma unroll
            for (int j = 0; j < 8; j++) {
                int2 mi = __ldg((const int2*)(mg + kt * 64 + j * 8 + 2 * tig));
                if (!mi.x) {
                    s[0][j][0] = NEGINF; s[0][j][2] = NEGINF;
                    s[1][j][0] = NEGINF; s[1][j][2] = NEGINF;
                }
                if (!mi.y) {
                    s[0][j][1] = NEGINF; s[0][j][3] = NEGINF;
                    s[1][j][1] = NEGINF; s[1][j][3] = NEGINF;
                }
            }
        }

        // ---- p = exp2(s) in f16x2; the cvt result IS the P fragment ----
        uint32_t pa[2][8][2];
        #pragma unroll
        for (int j = 0; j < 8; j++) {
            pa[0][j][0] = ex2h2(packh2(s[0][j][0], s[0][j][1]));
            pa[0][j][1] = ex2h2(packh2(s[0][j][2], s[0][j][3]));
            pa[1][j][0] = ex2h2(packh2(s[1][j][0], s[1][j][1]));
            pa[1][j][1] = ex2h2(packh2(s[1][j][2], s[1][j][3]));
        }

        // ---- O += P V^T ; l += P·1 (ones-MMA) ----
        #pragma unroll
        for (int m = 0; m < 4; m++) {
            uint32_t av0[4] = { pa[0][2 * m][0], pa[0][2 * m][1],
                                pa[0][2 * m + 1][0], pa[0][2 * m + 1][1] };
            uint32_t av1[4] = { pa[1][2 * m][0], pa[1][2 * m][1],
                                pa[1][2 * m + 1][0], pa[1][2 * m + 1][1] };
            const int kk = 16 * m + 2 * tig;
            #pragma unroll
            for (int j = 0; j < 8; j++) {
                const int rn = (j * 8 + g) * KLD + kk;
                uint32_t b0 = *(const uint32_t*)&Vs[rn];
                uint32_t b1 = *(const uint32_t*)&Vs[rn + 8];
                mma16(o[0][j], av0, b0, b1);
                mma16(o[1][j], av1, b0, b1);
            }
            mma16(lacc[0], av0, ONE2, ONE2);
            mma16(lacc[1], av1, ONE2, ONE2);
        }
        // no trailing barrier: next iteration's barrier protects buffers
    }

    // ---- finalize ----
    const float inv[2][2] = { {1.f / lacc[0][0], 1.f / lacc[0][2]},
                              {1.f / lacc[1][0], 1.f / lacc[1][2]} };

    #pragma unroll
    for (int i = 0; i < 2; i++) {
        float* cg = Ctx + ((size_t)(b * SEQ + q0 + qb + 16 * i)) * DMODEL + h * DK;
        #pragma unroll
        for (int j = 0; j < 8; j++) {
            const int col = j * 8 + 2 * tig;
            *(float2*)(cg + (size_t)g * DMODEL + col) =
                make_float2(o[i][j][0] * inv[i][0], o[i][j][1] * inv[i][0]);
            *(float2*)(cg + (size_t)(8 + g) * DMODEL + col) =
                make_float2(o[i][j][2] * inv[i][1], o[i][j][3] * inv[i][1]);
        }
    }
}

// ---------------------------------------------------------------------------
// Launcher.  Inputs: q, k, v, Wq, bq, Wk, bk, Wv, bv, Wo, bo, mask
// ---------------------------------------------------------------------------
extern "C" void kernel_launch(void* const* d_in, const int* in_sizes, int n_in,
                              void* d_out, int out_size)
{
    const float* q    = (const float*)d_in[0];
    const float* k    = (const float*)d_in[1];
    const float* v    = (const float*)d_in[2];
    const float* Wq   = (const float*)d_in[3];
    const float* bq   = (const float*)d_in[4];
    const float* Wk   = (const float*)d_in[5];
    const float* bk   = (const float*)d_in[6];
    const float* Wv   = (const float*)d_in[7];
    const float* bv   = (const float*)d_in[8];
    const float* Wo   = (const float*)d_in[9];
    const float* bo   = (const float*)d_in[10];
    const int*   mask = (const int*)d_in[11];
    float* out = (float*)d_out;

    __half *Qp, *Kp, *Vt;
    float *Ctx;
    cudaGetSymbolAddress((void**)&Qp,  g_Qp);
    cudaGetSymbolAddress((void**)&Kp,  g_Kp);
    cudaGetSymbolAddress((void**)&Vt,  g_Vt);
    cudaGetSymbolAddress((void**)&Ctx, g_Ctx);

    cudaFuncSetAttribute(attn_tc, cudaFuncAttributeMaxDynamicSharedMemorySize,
                         ATT_SMEM);

    // Q scale folds 1/sqrt(dk) AND log2(e): scores emerge in exp2 domain.
    const float qscale = 0.125f * 1.44269504088896340736f;

    dim3 qkvgrid(DMODEL / GBN, MROWS / GBM, 3);   // (6, 64, 3)
    qkv_gemm<<<qkvgrid, 256>>>(q, k, v, Wq, bq, Wk, bk, Wv, bv,
                               Qp, Kp, Vt, qscale);

    dim3 agrid(SEQ / 128, BS * HEADS);            // (32, 24)
    attn_tc<<<agrid, 128, ATT_SMEM>>>(Qp, Kp, Vt, mask, Ctx);

    dim3 ogrid(DMODEL / GBN, MROWS / GBM);        // (6, 64)
    o_gemm<<<ogrid, 256>>>(Ctx, Wo, bo, out);
}